// round 2
// baseline (speedup 1.0000x reference)
#include <cuda_runtime.h>
#include <cstdint>

// ---------------------------------------------------------------------------
// TTLinear: y[4096,4096] = x[4096,1024] @ W[1024,4096] + bias
// W is collapsed from the 4 TT cores each launch (deterministic, ~10us),
// then a tf32 mma.sync tiled GEMM does the heavy lifting.
// ---------------------------------------------------------------------------

#define TOKENS 4096
#define KDIM   1024
#define NDIM   4096

// Scratch (static __device__ allocation is the sanctioned workaround)
__device__ float g_G2[64 * 64 * 16];        // [(m1 m2)][(n1 n2)][r2]   256 KB
__device__ float g_G3[256 * 512 * 16];      // [(m1m2m3)][(n1n2n3)][r3]   8 MB
__device__ float g_W [KDIM * NDIM];         // [f][o] row-major          16 MB

// ---------------- W builders ----------------

__global__ void k_g2(const float* __restrict__ c0, const float* __restrict__ c1) {
    int idx = blockIdx.x * 256 + threadIdx.x;       // 65536
    int r2 = idx & 15;
    int N2 = (idx >> 4) & 63;
    int M2 = idx >> 10;
    int m1 = M2 >> 3, m2 = M2 & 7, n1 = N2 >> 3, n2 = N2 & 7;
    float s = 0.f;
#pragma unroll
    for (int r1 = 0; r1 < 16; r1++)
        s += c0[(m1 * 8 + n1) * 16 + r1] * c1[((r1 * 8 + m2) * 8 + n2) * 16 + r2];
    g_G2[idx] = s;
}

__global__ void k_g3(const float* __restrict__ c2) {
    int idx = blockIdx.x * 256 + threadIdx.x;       // 2097152
    int r3 = idx & 15;
    int N3 = (idx >> 4) & 511;
    int M3 = idx >> 13;
    int N2 = N3 >> 3, n3 = N3 & 7, M2 = M3 >> 2, m3 = M3 & 3;
    const float* g2 = &g_G2[(M2 * 64 + N2) * 16];
    float s = 0.f;
#pragma unroll
    for (int r2 = 0; r2 < 16; r2++)
        s += g2[r2] * c2[((r2 * 4 + m3) * 8 + n3) * 16 + r3];
    g_G3[idx] = s;
}

__global__ void k_w(const float* __restrict__ c3) {
    int idx = blockIdx.x * 256 + threadIdx.x;       // 4194304, idx = f*4096+o
    int o = idx & 4095, f = idx >> 12;
    int n4 = o & 7, N3 = o >> 3;
    int m4 = f & 3, M3 = f >> 2;
    const float* g3 = &g_G3[(M3 * 512 + N3) * 16];
    float s = 0.f;
#pragma unroll
    for (int r3 = 0; r3 < 16; r3++)
        s += g3[r3] * c3[(r3 * 4 + m4) * 8 + n4];
    // pre-round to tf32 so the GEMM's raw-bit B operand is exact
    uint32_t u; asm("cvt.rna.tf32.f32 %0, %1;" : "=r"(u) : "f"(s));
    g_W[idx] = __uint_as_float(u);
}

// ---------------- GEMM ----------------

#define BM 128
#define BN 128
#define BK 32
#define ASTR 36     // padded A row stride (conflict-free for frag loads)
#define BSTR 132    // padded B row stride
#define A_STAGE (BM * ASTR)
#define B_STAGE (BK * BSTR)
#define SMEM_BYTES ((2 * A_STAGE + 2 * B_STAGE) * 4)   // 70656

__device__ __forceinline__ void cp_async16(void* s, const void* g) {
    uint32_t sa = (uint32_t)__cvta_generic_to_shared(s);
    asm volatile("cp.async.cg.shared.global [%0], [%1], 16;\n" :: "r"(sa), "l"(g));
}

__device__ __forceinline__ uint32_t f2tf32(float f) {
    uint32_t u; asm("cvt.rna.tf32.f32 %0, %1;" : "=r"(u) : "f"(f)); return u;
}

__device__ __forceinline__ void mma8(float d[4], const uint32_t a[4], const uint32_t b[2]) {
    asm volatile(
        "mma.sync.aligned.m16n8k8.row.col.f32.tf32.tf32.f32 "
        "{%0,%1,%2,%3}, {%4,%5,%6,%7}, {%8,%9}, {%0,%1,%2,%3};\n"
        : "+f"(d[0]), "+f"(d[1]), "+f"(d[2]), "+f"(d[3])
        : "r"(a[0]), "r"(a[1]), "r"(a[2]), "r"(a[3]), "r"(b[0]), "r"(b[1]));
}

__global__ void __launch_bounds__(256)
gemm_kernel(const float* __restrict__ x, const float* __restrict__ bias,
            float* __restrict__ out) {
    extern __shared__ float smem[];
    float* As = smem;                    // [2][128][ASTR]
    float* Bs = smem + 2 * A_STAGE;      // [2][32][BSTR]

    const int tid  = threadIdx.x;
    const int warp = tid >> 5, lane = tid & 31;
    const int wm = (warp >> 2) * 64;     // warp M offset (0/64)
    const int wn = (warp & 3) * 32;      // warp N offset (0/32/64/96)
    const int m0 = blockIdx.y * BM;
    const int n0 = blockIdx.x * BN;

    float acc[4][4][4];
#pragma unroll
    for (int i = 0; i < 4; i++)
#pragma unroll
        for (int j = 0; j < 4; j++)
#pragma unroll
            for (int k = 0; k < 4; k++) acc[i][j][k] = 0.f;

    auto load_stage = [&](int s, int k0) {
        float* A = As + s * A_STAGE;
        float* B = Bs + s * B_STAGE;
#pragma unroll
        for (int i = 0; i < 4; i++) {                 // A: 128x32 floats
            int q = i * 256 + tid;
            int r = q >> 3, c = (q & 7) << 2;
            cp_async16(&A[r * ASTR + c], &x[(m0 + r) * KDIM + k0 + c]);
        }
#pragma unroll
        for (int i = 0; i < 4; i++) {                 // B: 32x128 floats
            int q = i * 256 + tid;
            int r = q >> 5, c = (q & 31) << 2;
            cp_async16(&B[r * BSTR + c], &g_W[(k0 + r) * NDIM + n0 + c]);
        }
    };

    load_stage(0, 0);
    asm volatile("cp.async.commit_group;\n" ::);

    const int NT = KDIM / BK;   // 32
    for (int kt = 0; kt < NT; kt++) {
        if (kt + 1 < NT) {
            load_stage((kt + 1) & 1, (kt + 1) * BK);
            asm volatile("cp.async.commit_group;\n" ::);
            asm volatile("cp.async.wait_group 1;\n" ::);
        } else {
            asm volatile("cp.async.wait_group 0;\n" ::);
        }
        __syncthreads();

        const float* A = As + (kt & 1) * A_STAGE;
        const float* B = Bs + (kt & 1) * B_STAGE;

#pragma unroll
        for (int ks = 0; ks < 4; ks++) {              // 4 x k8 per BK=32
            uint32_t af[4][4];
            const int ar = wm + (lane >> 2);
            const int ac = ks * 8 + (lane & 3);
#pragma unroll
            for (int mi = 0; mi < 4; mi++) {
                const float* Ab = A + (ar + mi * 16) * ASTR + ac;
                af[mi][0] = f2tf32(Ab[0]);
                af[mi][1] = f2tf32(Ab[8 * ASTR]);
                af[mi][2] = f2tf32(Ab[4]);
                af[mi][3] = f2tf32(Ab[8 * ASTR + 4]);
            }
            uint32_t bf[4][2];
            const int br = ks * 8 + (lane & 3);
            const int bc = wn + (lane >> 2);
#pragma unroll
            for (int ni = 0; ni < 4; ni++) {
                bf[ni][0] = __float_as_uint(B[br * BSTR + bc + ni * 8]);
                bf[ni][1] = __float_as_uint(B[(br + 4) * BSTR + bc + ni * 8]);
            }
#pragma unroll
            for (int mi = 0; mi < 4; mi++)
#pragma unroll
                for (int ni = 0; ni < 4; ni++)
                    mma8(acc[mi][ni], af[mi], bf[ni]);
        }
        __syncthreads();
    }

    // epilogue: + bias, f32 out
#pragma unroll
    for (int mi = 0; mi < 4; mi++) {
        int row = m0 + wm + mi * 16 + (lane >> 2);
#pragma unroll
        for (int ni = 0; ni < 4; ni++) {
            int col = n0 + wn + ni * 8 + 2 * (lane & 3);
            float b0 = bias[col], b1 = bias[col + 1];
            float2 v0 = make_float2(acc[mi][ni][0] + b0, acc[mi][ni][1] + b1);
            float2 v1 = make_float2(acc[mi][ni][2] + b0, acc[mi][ni][3] + b1);
            *reinterpret_cast<float2*>(&out[row * NDIM + col]) = v0;
            *reinterpret_cast<float2*>(&out[(row + 8) * NDIM + col]) = v1;
        }
    }
}

// ---------------- launch ----------------

extern "C" void kernel_launch(void* const* d_in, const int* in_sizes, int n_in,
                              void* d_out, int out_size) {
    const float* x     = (const float*)d_in[0];
    const float* core0 = (const float*)d_in[1];
    const float* core1 = (const float*)d_in[2];
    const float* core2 = (const float*)d_in[3];
    const float* core3 = (const float*)d_in[4];
    const float* bias  = (const float*)d_in[5];
    float* out = (float*)d_out;

    k_g2<<<256, 256>>>(core0, core1);
    k_g3<<<8192, 256>>>(core2);
    k_w<<<16384, 256>>>(core3);

    cudaFuncSetAttribute(gemm_kernel,
                         cudaFuncAttributeMaxDynamicSharedMemorySize, SMEM_BYTES);
    gemm_kernel<<<dim3(NDIM / BN, TOKENS / BM), 256, SMEM_BYTES>>>(x, bias, out);
}